// round 3
// baseline (speedup 1.0000x reference)
#include <cuda_runtime.h>

#define NB 8
#define CC 64
#define TT 256
#define VQ 90
#define VK 50
#define SS 4
#define LAG 4
#define NLAG (LAG + 1)
#define TQ (TT - LAG)                 // 252
#define COLS_Q (TQ * VQ)              // 22680
#define COLS_T (TT * VQ)              // 23040
#define COLS_K (TT * VK)              // 12800
#define BN_EPS 1e-5f

typedef unsigned long long ull;

// ---------------- packed f32x2 helpers (sm_103a FFMA2 path) ----------------
__device__ __forceinline__ ull fdup(float x) {
    ull r; unsigned xi = __float_as_uint(x);
    asm("mov.b64 %0, {%1, %1};" : "=l"(r) : "r"(xi));
    return r;
}
__device__ __forceinline__ ull fpack(float lo, float hi) {
    ull r; unsigned a = __float_as_uint(lo), b = __float_as_uint(hi);
    asm("mov.b64 %0, {%1, %2};" : "=l"(r) : "r"(a), "r"(b));
    return r;
}
__device__ __forceinline__ void ffma2(ull& acc, ull a, ull b) {
    asm("fma.rn.f32x2 %0, %1, %2, %0;" : "+l"(acc) : "l"(a), "l"(b));
}
__device__ __forceinline__ void funpack(ull v, float& lo, float& hi) {
    unsigned a, b;
    asm("mov.b64 {%0, %1}, %2;" : "=r"(a), "=r"(b) : "l"(v));
    lo = __uint_as_float(a); hi = __uint_as_float(b);
}

// ---------------- scratch (static device memory; no allocations) ----------------
__device__ float g_q   [NB * SS * CC * COLS_Q];
__device__ float g_k   [NB * SS * CC * COLS_K];
__device__ float g_v   [NB * CC * COLS_K];
__device__ float g_y   [NB * SS * CC * COLS_T];
__device__ float g_o1  [NB * CC * COLS_T];
__device__ float g_d   [NB * CC * COLS_T];
__device__ float g_att5[NLAG * NB * SS * VQ * VK];
__device__ float g_att [NB * SS * VQ * VK];
__device__ float g_stats[2 * CC * 2];

// ---------------- zero kernel ----------------
__global__ void zero_kernel(float* p, int n) {
    int i = blockIdx.x * blockDim.x + threadIdx.x;
    if (i < n) p[i] = 0.f;
}

// ---------------- conv1x1 GEMM, 64 rows x 128 cols per block, f32x2 ----------------
// O[n][r][col] = sum_k W[r][k] X[n][k][col] + b[r]
__global__ __launch_bounds__(256) void gemm_bias(
    const float* __restrict__ W, const float* __restrict__ bias,
    const float* __restrict__ X, float* __restrict__ O,
    int K, int cols, int rsB, long bsB, long bsC)
{
    __shared__ float  Ws[32][64];     // [k][r] transposed
    __shared__ float4 Xs4[32][32];    // [k][c/4]
    int tid = threadIdx.x;
    int tx = tid & 15, ty = tid >> 4;
    int n = blockIdx.z;
    int row0 = blockIdx.y * 64;
    int col0 = blockIdx.x * 128;
    const float* Xn = X + (long)n * bsB;

    ull acc[4][4];
#pragma unroll
    for (int i = 0; i < 4; i++)
#pragma unroll
        for (int j = 0; j < 4; j++) acc[i][j] = 0ull;

#pragma unroll 1
    for (int kc = 0; kc < K; kc += 32) {
        // Ws[k][r] = W[(row0+r)*K + kc+k]
        for (int idx = tid; idx < 32 * 64; idx += 256) {
            int k = idx >> 6, r = idx & 63;
            Ws[k][r] = W[(long)(row0 + r) * K + kc + k];
        }
        // Xs: 32 x 128 floats as float4
        for (int idx = tid; idx < 32 * 32; idx += 256) {
            int k = idx >> 5, c4 = idx & 31;
            int col = col0 + c4 * 4;
            float4 v = make_float4(0.f, 0.f, 0.f, 0.f);
            if (col < cols)
                v = *reinterpret_cast<const float4*>(&Xn[(long)(kc + k) * rsB + col]);
            Xs4[k][c4] = v;
        }
        __syncthreads();
#pragma unroll
        for (int k = 0; k < 32; k++) {
            float4 av = *reinterpret_cast<const float4*>(&Ws[k][ty * 4]);
            ull ad[4];
            ad[0] = fdup(av.x); ad[1] = fdup(av.y);
            ad[2] = fdup(av.z); ad[3] = fdup(av.w);
            float4 b0 = Xs4[k][tx * 2];
            float4 b1 = Xs4[k][tx * 2 + 1];
            ull bp[4];
            bp[0] = fpack(b0.x, b0.y); bp[1] = fpack(b0.z, b0.w);
            bp[2] = fpack(b1.x, b1.y); bp[3] = fpack(b1.z, b1.w);
#pragma unroll
            for (int i = 0; i < 4; i++)
#pragma unroll
                for (int j = 0; j < 4; j++) ffma2(acc[i][j], ad[i], bp[j]);
        }
        __syncthreads();
    }
#pragma unroll
    for (int i = 0; i < 4; i++) {
        int r = row0 + ty * 4 + i;
        float bv = bias[r];
        float* orow = O + (long)n * bsC + (long)r * cols;
#pragma unroll
        for (int j = 0; j < 4; j++) {
            int col = col0 + tx * 8 + 2 * j;
            if (col < cols) {
                float lo, hi; funpack(acc[i][j], lo, hi);
                *reinterpret_cast<float2*>(&orow[col]) = make_float2(lo + bv, hi + bv);
            }
        }
    }
}

// ---------------- 5-lag attention scores, f32x2, register sliding window ----------------
// att5[l][n][s][vq][vk] += sum_{c in chunk, t<TQ} q[n,s,c,t,vq] * k[n,s,c,t+l,vk]
#define CHT 36
__global__ __launch_bounds__(416) void scores_kernel(
    const float* __restrict__ q, const float* __restrict__ k,
    float* __restrict__ att5)
{
    __shared__ float q_s[CHT][90];
    __shared__ float k_s[CHT + 4][52];
    int tid = threadIdx.x;
    int ns = blockIdx.x;              // n*S+s
    int n = ns >> 2, s = ns & 3;
    int c0 = blockIdx.y * 4;          // 16 chunks of 4 channels
    int gq = tid % 30, gk = tid / 30; // gk<13 valid
    int vq0 = gq * 3, vk0 = gk * 4;
    bool active = tid < 390;

    ull acc[NLAG][3][2];
#pragma unroll
    for (int l = 0; l < NLAG; l++)
#pragma unroll
        for (int i = 0; i < 3; i++)
#pragma unroll
            for (int jp = 0; jp < 2; jp++) acc[l][i][jp] = 0ull;

#pragma unroll 1
    for (int cc = 0; cc < 4; cc++) {
        int sc = s * CC + c0 + cc;
        const float* qrow = q + (long)(n * SS * CC + sc) * COLS_Q;
        const float* krow = k + (long)(n * SS * CC + sc) * COLS_K;
#pragma unroll 1
        for (int ch = 0; ch < 7; ch++) {
            int t0 = ch * CHT;
            for (int idx = tid; idx < CHT * 90; idx += 416) {
                int r = idx / 90, c = idx % 90;
                q_s[r][c] = qrow[(t0 + r) * VQ + c];
            }
            for (int idx = tid; idx < (CHT + 4) * 52; idx += 416) {
                int r = idx / 52, c = idx % 52;
                k_s[r][c] = (c < VK) ? krow[(t0 + r) * VK + c] : 0.f;
            }
            __syncthreads();
            if (active) {
                ull kw[2][5];
#pragma unroll
                for (int sl = 0; sl < 4; sl++) {
                    kw[0][sl] = *reinterpret_cast<const ull*>(&k_s[sl][vk0]);
                    kw[1][sl] = *reinterpret_cast<const ull*>(&k_s[sl][vk0 + 2]);
                }
#pragma unroll
                for (int u = 0; u < CHT; u++) {
                    kw[0][(u + 4) % 5] = *reinterpret_cast<const ull*>(&k_s[u + 4][vk0]);
                    kw[1][(u + 4) % 5] = *reinterpret_cast<const ull*>(&k_s[u + 4][vk0 + 2]);
                    ull qd[3];
#pragma unroll
                    for (int i = 0; i < 3; i++) qd[i] = fdup(q_s[u][vq0 + i]);
#pragma unroll
                    for (int l = 0; l < NLAG; l++) {
#pragma unroll
                        for (int i = 0; i < 3; i++) {
                            ffma2(acc[l][i][0], qd[i], kw[0][(u + l) % 5]);
                            ffma2(acc[l][i][1], qd[i], kw[1][(u + l) % 5]);
                        }
                    }
                }
            }
            __syncthreads();
        }
    }
    if (active) {
#pragma unroll
        for (int l = 0; l < NLAG; l++)
#pragma unroll
            for (int i = 0; i < 3; i++)
#pragma unroll
                for (int jp = 0; jp < 2; jp++) {
                    float lo, hi; funpack(acc[l][i][jp], lo, hi);
                    int vk = vk0 + 2 * jp;
                    long base = (((long)(l * NB + n) * SS + s) * VQ + vq0 + i) * VK;
                    if (vk < VK)     atomicAdd(&att5[base + vk], lo);
                    if (vk + 1 < VK) atomicAdd(&att5[base + vk + 1], hi);
                }
    }
}

// ---------------- (max+mean)/2 over lags, /scale, softmax over vk ----------------
__global__ void softmax_kernel(const float* __restrict__ att5, float* __restrict__ att)
{
    int r = blockIdx.x;               // 2880 rows
    int tid = threadIdx.x;            // 64
    __shared__ float red[64];
    const float halfInv = 0.5f / sqrtf((float)(CC * TQ));
    float p = -1e30f;
    if (tid < VK) {
        float mx = -1e30f, sm = 0.f;
#pragma unroll
        for (int l = 0; l < NLAG; l++) {
            float v = att5[((long)l * (NB * SS * VQ) + r) * VK + tid];
            mx = fmaxf(mx, v);
            sm += v;
        }
        p = (mx + sm * 0.2f) * halfInv;
    }
    red[tid] = p;
    __syncthreads();
    for (int o = 32; o > 0; o >>= 1) {
        if (tid < o) red[tid] = fmaxf(red[tid], red[tid + o]);
        __syncthreads();
    }
    float m = red[0];
    __syncthreads();
    float e = (tid < VK) ? expf(p - m) : 0.f;
    red[tid] = e;
    __syncthreads();
    for (int o = 32; o > 0; o >>= 1) {
        if (tid < o) red[tid] += red[tid + o];
        __syncthreads();
    }
    if (tid < VK) att[(long)r * VK + tid] = e / red[0];
}

// ---------------- y[n,s,c,t,vq] = sum_vk att[n,s,vq,vk] * v[n,c,t,vk], f32x2 ----------------
__global__ __launch_bounds__(256) void ygemm_kernel(
    const float* __restrict__ att, const float* __restrict__ v,
    float* __restrict__ y)
{
    __shared__ ull   att_p[VK][48];   // [vk][vq-pair], 45 used
    __shared__ float v_s[64][VK];
    int tid = threadIdx.x;
    int tx = tid & 15, ty = tid >> 4;
    int ns = blockIdx.y;
    int n = ns >> 2;
    int ct0 = blockIdx.x * 64;
    int vqp0 = tx * 3;

    for (int idx = tid; idx < 45 * VK; idx += 256) {
        int p = idx / VK, vk = idx % VK;
        const float* ab = att + (long)ns * (VQ * VK);
        att_p[vk][p] = fpack(ab[(2 * p) * VK + vk], ab[(2 * p + 1) * VK + vk]);
    }
    for (int idx = tid; idx < VK * 3; idx += 256)
        att_p[idx / 3][45 + idx % 3] = 0ull;
    const float* vb = v + (long)n * CC * COLS_K + (long)ct0 * VK;
    for (int idx = tid; idx < 64 * VK; idx += 256)
        v_s[idx / VK][idx % VK] = vb[idx];
    __syncthreads();

    ull acc[4][3];
#pragma unroll
    for (int i = 0; i < 4; i++)
#pragma unroll
        for (int j = 0; j < 3; j++) acc[i][j] = 0ull;

#pragma unroll 10
    for (int vk = 0; vk < VK; vk++) {
        ull ad[4];
#pragma unroll
        for (int i = 0; i < 4; i++) ad[i] = fdup(v_s[ty * 4 + i][vk]);
        ull bp[3];
#pragma unroll
        for (int j = 0; j < 3; j++) bp[j] = att_p[vk][vqp0 + j];
#pragma unroll
        for (int i = 0; i < 4; i++)
#pragma unroll
            for (int j = 0; j < 3; j++) ffma2(acc[i][j], ad[i], bp[j]);
    }
    long ybase = (long)ns * (CC * TT * VQ);
#pragma unroll
    for (int i = 0; i < 4; i++) {
        long ct = ct0 + ty * 4 + i;
#pragma unroll
        for (int j = 0; j < 3; j++) {
            int vqp = vqp0 + j;
            if (vqp < 45) {
                float lo, hi; funpack(acc[i][j], lo, hi);
                *reinterpret_cast<float2*>(&y[ybase + ct * VQ + 2 * vqp]) =
                    make_float2(lo, hi);
            }
        }
    }
}

// ---------------- per-channel BN stats (training mode, biased var) ----------------
__global__ void stats_kernel(const float* __restrict__ o1, const float* __restrict__ d,
                             float* __restrict__ stats)
{
    int co = blockIdx.x;
    int which = blockIdx.y;
    const float* src = which ? d : o1;
    int tid = threadIdx.x;            // 256
    float sum = 0.f, sq = 0.f;
    for (int idx = tid; idx < NB * (COLS_T / 4); idx += 256) {
        int n = idx / (COLS_T / 4), c4 = idx % (COLS_T / 4);
        float4 x = *reinterpret_cast<const float4*>(
            &src[((long)n * CC + co) * COLS_T + c4 * 4]);
        sum += x.x + x.y + x.z + x.w;
        sq += x.x * x.x + x.y * x.y + x.z * x.z + x.w * x.w;
    }
    __shared__ float s1[256], s2[256];
    s1[tid] = sum; s2[tid] = sq;
    __syncthreads();
    for (int o = 128; o > 0; o >>= 1) {
        if (tid < o) { s1[tid] += s1[tid + o]; s2[tid] += s2[tid + o]; }
        __syncthreads();
    }
    if (tid == 0) {
        float M = (float)(NB * COLS_T);
        float mean = s1[0] / M;
        float var = s2[0] / M - mean * mean;
        stats[(which * CC + co) * 2 + 0] = mean;
        stats[(which * CC + co) * 2 + 1] = rsqrtf(var + BN_EPS);
    }
}

// ---------------- BN both paths + add + leaky relu (vectorized) ----------------
__global__ void final_kernel(const float* __restrict__ o1, const float* __restrict__ d,
                             const float* __restrict__ stats,
                             const float* __restrict__ gout, const float* __restrict__ bout,
                             const float* __restrict__ gdown, const float* __restrict__ bdown,
                             float* __restrict__ out)
{
    long i4 = (long)blockIdx.x * blockDim.x + threadIdx.x;
    long total4 = (long)NB * CC * COLS_T / 4;
    if (i4 >= total4) return;
    long idx = i4 * 4;
    int co = (int)((idx / COLS_T) % CC);
    float mo = stats[co * 2 + 0], iso = stats[co * 2 + 1];
    float md = stats[(CC + co) * 2 + 0], isd = stats[(CC + co) * 2 + 1];
    float so = iso * gout[co], sd = isd * gdown[co];
    float bo = bout[co] - mo * so, bd = bdown[co] - md * sd;
    float4 a = *reinterpret_cast<const float4*>(&o1[idx]);
    float4 b = *reinterpret_cast<const float4*>(&d[idx]);
    float4 r;
    float v;
    v = a.x * so + bo + b.x * sd + bd; r.x = v > 0.f ? v : 0.1f * v;
    v = a.y * so + bo + b.y * sd + bd; r.y = v > 0.f ? v : 0.1f * v;
    v = a.z * so + bo + b.z * sd + bd; r.z = v > 0.f ? v : 0.1f * v;
    v = a.w * so + bo + b.w * sd + bd; r.w = v > 0.f ? v : 0.1f * v;
    *reinterpret_cast<float4*>(&out[idx]) = r;
}

// ---------------- launch ----------------
extern "C" void kernel_launch(void* const* d_in, const int* in_sizes, int n_in,
                              void* d_out, int out_size)
{
    const float* x_q   = (const float*)d_in[0];
    const float* x_k   = (const float*)d_in[1];
    const float* x_v   = (const float*)d_in[2];
    const float* Wq    = (const float*)d_in[3];
    const float* bq    = (const float*)d_in[4];
    const float* Wk    = (const float*)d_in[5];
    const float* bk    = (const float*)d_in[6];
    const float* Wv    = (const float*)d_in[7];
    const float* bv    = (const float*)d_in[8];
    const float* Wout  = (const float*)d_in[9];
    const float* bout  = (const float*)d_in[10];
    const float* g_out = (const float*)d_in[11];
    const float* b_out = (const float*)d_in[12];
    const float* Wdown = (const float*)d_in[13];
    const float* bdown = (const float*)d_in[14];
    const float* g_dn  = (const float*)d_in[15];
    const float* b_dn  = (const float*)d_in[16];

    float *q, *k, *v, *y, *o1, *db, *att5, *att, *stats;
    cudaGetSymbolAddress((void**)&q,     g_q);
    cudaGetSymbolAddress((void**)&k,     g_k);
    cudaGetSymbolAddress((void**)&v,     g_v);
    cudaGetSymbolAddress((void**)&y,     g_y);
    cudaGetSymbolAddress((void**)&o1,    g_o1);
    cudaGetSymbolAddress((void**)&db,    g_d);
    cudaGetSymbolAddress((void**)&att5,  g_att5);
    cudaGetSymbolAddress((void**)&att,   g_att);
    cudaGetSymbolAddress((void**)&stats, g_stats);

    int natt5 = NLAG * NB * SS * VQ * VK;
    zero_kernel<<<(natt5 + 255) / 256, 256>>>(att5, natt5);

    // projections
    gemm_bias<<<dim3((COLS_Q + 127) / 128, (SS * CC) / 64, NB), 256>>>(
        Wq, bq, x_q, q, CC, COLS_Q, COLS_T, (long)CC * COLS_T, (long)SS * CC * COLS_Q);
    gemm_bias<<<dim3(COLS_K / 128, (SS * CC) / 64, NB), 256>>>(
        Wk, bk, x_k, k, CC, COLS_K, COLS_K, (long)CC * COLS_K, (long)SS * CC * COLS_K);
    gemm_bias<<<dim3(COLS_K / 128, 1, NB), 256>>>(
        Wv, bv, x_v, v, CC, COLS_K, COLS_K, (long)CC * COLS_K, (long)CC * COLS_K);

    // multi-lag scores + softmax
    scores_kernel<<<dim3(NB * SS, 16), 416>>>(q, k, att5);
    softmax_kernel<<<NB * SS * VQ, 64>>>(att5, att);

    // y = att @ v
    ygemm_kernel<<<dim3((CC * TT) / 64, NB * SS), 256>>>(att, v, y);

    // output / downsample projections
    gemm_bias<<<dim3(COLS_T / 128, 1, NB), 256>>>(
        Wout, bout, y, o1, SS * CC, COLS_T, COLS_T, (long)SS * CC * COLS_T, (long)CC * COLS_T);
    gemm_bias<<<dim3(COLS_T / 128, 1, NB), 256>>>(
        Wdown, bdown, x_q, db, CC, COLS_T, COLS_T, (long)CC * COLS_T, (long)CC * COLS_T);

    // BN stats + fused epilogue
    stats_kernel<<<dim3(CC, 2), 256>>>(o1, db, stats);
    long total4 = (long)NB * CC * COLS_T / 4;
    final_kernel<<<(unsigned)((total4 + 255) / 256), 256>>>(
        o1, db, stats, g_out, b_out, g_dn, b_dn, (float*)d_out);
}

// round 5
// speedup vs baseline: 1.7715x; 1.7715x over previous
#include <cuda_runtime.h>

#define NB 8
#define CC 64
#define TT 256
#define VQ 90
#define VK 50
#define SS 4
#define LAG 4
#define NLAG (LAG + 1)
#define TQ (TT - LAG)                 // 252
#define COLS_Q (TQ * VQ)              // 22680
#define COLS_T (TT * VQ)              // 23040
#define COLS_K (TT * VK)              // 12800
#define BN_EPS 1e-5f

// ---------------- tf32 mma helpers ----------------
__device__ __forceinline__ unsigned f2tf32(float x) {
    unsigned r;
    asm("cvt.rna.tf32.f32 %0, %1;" : "=r"(r) : "f"(x));
    return r;
}
__device__ __forceinline__ void mma_tf32(
    float& c0, float& c1, float& c2, float& c3,
    unsigned a0, unsigned a1, unsigned a2, unsigned a3,
    unsigned b0, unsigned b1)
{
    asm("mma.sync.aligned.m16n8k8.row.col.f32.tf32.tf32.f32 "
        "{%0,%1,%2,%3},{%4,%5,%6,%7},{%8,%9},{%0,%1,%2,%3};"
        : "+f"(c0), "+f"(c1), "+f"(c2), "+f"(c3)
        : "r"(a0), "r"(a1), "r"(a2), "r"(a3), "r"(b0), "r"(b1));
}

// ---------------- scratch (static device memory; no allocations) ----------------
__device__ float g_q   [NB * SS * CC * COLS_Q];
__device__ float g_k   [NB * SS * CC * COLS_K];
__device__ float g_v   [NB * CC * COLS_K];
__device__ float g_y   [NB * SS * CC * COLS_T];
__device__ float g_o1  [NB * CC * COLS_T];
__device__ float g_d   [NB * CC * COLS_T];
__device__ float g_att5[NLAG * NB * SS * VQ * VK];
__device__ float g_att [NB * SS * VQ * VK];
__device__ float g_stats[2 * CC * 2];

// ---------------- zero kernel ----------------
__global__ void zero_kernel(float* p, int n) {
    int i = blockIdx.x * blockDim.x + threadIdx.x;
    if (i < n) p[i] = 0.f;
}

// ---------------- conv1x1 GEMM via tf32 mma: O[n][r][col] = sum_k W[r][k] X[n][k][col] + b[r] ----------------
// Block tile: 64 rows x 128 cols, K-chunk 32. 4 warps (2 M x 2 N), warp tile 32x64.
__global__ __launch_bounds__(128) void gemm_tf32(
    const float* __restrict__ W, const float* __restrict__ bias,
    const float* __restrict__ X, float* __restrict__ O,
    int K, int cols, int rsB, long bsB, long bsC)
{
    __shared__ unsigned Ws[64][36];   // [m][k], stride 36 -> conflict-free frags
    __shared__ unsigned Xs[32][136];  // [k][n], stride 136 -> conflict-free frags
    int tid = threadIdx.x;
    int lane = tid & 31;
    int w = tid >> 5;
    int wm = w & 1, wn = w >> 1;
    int lr = lane >> 2, lc = lane & 3;
    int n = blockIdx.z;
    int row0 = blockIdx.y * 64;
    int col0 = blockIdx.x * 128;
    const float* Xn = X + (long)n * bsB;

    float acc[2][8][4];
#pragma unroll
    for (int mt = 0; mt < 2; mt++)
#pragma unroll
        for (int nt = 0; nt < 8; nt++)
#pragma unroll
            for (int e = 0; e < 4; e++) acc[mt][nt][e] = 0.f;

    for (int kc = 0; kc < K; kc += 32) {
        // Ws[m][k] <- W[(row0+m)*K + kc+k]
#pragma unroll
        for (int it = 0; it < 4; it++) {
            int idx = tid + it * 128;          // 64 rows x 8 float4
            int r = idx >> 3, q4 = idx & 7;
            float4 wv = *reinterpret_cast<const float4*>(&W[(long)(row0 + r) * K + kc + q4 * 4]);
            Ws[r][q4 * 4 + 0] = f2tf32(wv.x);
            Ws[r][q4 * 4 + 1] = f2tf32(wv.y);
            Ws[r][q4 * 4 + 2] = f2tf32(wv.z);
            Ws[r][q4 * 4 + 3] = f2tf32(wv.w);
        }
        // Xs[k][c] <- X[(kc+k)*rsB + col0+c]
#pragma unroll
        for (int it = 0; it < 8; it++) {
            int idx = tid + it * 128;          // 32 rows x 32 float4
            int kk = idx >> 5, c4 = idx & 31;
            int col = col0 + c4 * 4;
            float4 xv = make_float4(0.f, 0.f, 0.f, 0.f);
            if (col < cols)
                xv = *reinterpret_cast<const float4*>(&Xn[(long)(kc + kk) * rsB + col]);
            Xs[kk][c4 * 4 + 0] = f2tf32(xv.x);
            Xs[kk][c4 * 4 + 1] = f2tf32(xv.y);
            Xs[kk][c4 * 4 + 2] = f2tf32(xv.z);
            Xs[kk][c4 * 4 + 3] = f2tf32(xv.w);
        }
        __syncthreads();
#pragma unroll
        for (int kk = 0; kk < 32; kk += 8) {
            unsigned a[2][4];
#pragma unroll
            for (int mt = 0; mt < 2; mt++) {
                int m0 = wm * 32 + mt * 16;
                a[mt][0] = Ws[m0 + lr][kk + lc];
                a[mt][1] = Ws[m0 + 8 + lr][kk + lc];
                a[mt][2] = Ws[m0 + lr][kk + 4 + lc];
                a[mt][3] = Ws[m0 + 8 + lr][kk + 4 + lc];
            }
            unsigned b[8][2];
#pragma unroll
            for (int nt = 0; nt < 8; nt++) {
                int n0 = wn * 64 + nt * 8;
                b[nt][0] = Xs[kk + lc][n0 + lr];
                b[nt][1] = Xs[kk + 4 + lc][n0 + lr];
            }
#pragma unroll
            for (int mt = 0; mt < 2; mt++)
#pragma unroll
                for (int nt = 0; nt < 8; nt++)
                    mma_tf32(acc[mt][nt][0], acc[mt][nt][1], acc[mt][nt][2], acc[mt][nt][3],
                             a[mt][0], a[mt][1], a[mt][2], a[mt][3],
                             b[nt][0], b[nt][1]);
        }
        __syncthreads();
    }
    // epilogue
#pragma unroll
    for (int mt = 0; mt < 2; mt++) {
        int r0 = row0 + wm * 32 + mt * 16 + lr;
        float bv0 = bias[r0], bv8 = bias[r0 + 8];
        float* orow0 = O + (long)n * bsC + (long)r0 * cols;
        float* orow8 = orow0 + (long)8 * cols;
#pragma unroll
        for (int nt = 0; nt < 8; nt++) {
            int col = col0 + wn * 64 + nt * 8 + lc * 2;
            if (col < cols) {
                *reinterpret_cast<float2*>(&orow0[col]) =
                    make_float2(acc[mt][nt][0] + bv0, acc[mt][nt][1] + bv0);
                *reinterpret_cast<float2*>(&orow8[col]) =
                    make_float2(acc[mt][nt][2] + bv8, acc[mt][nt][3] + bv8);
            }
        }
    }
}

// ---------------- 5-lag attention scores via tf32 mma ----------------
// For block (ns, c-chunk): C[vq, (l,vk)] += sum_{c in chunk, t} q[c,t,vq] * k[c,t+l,vk]
// A = q_s[t][vq] (M=96 padded), B = k_s[t+l][vk] (logical N = 5*56 = 280).
// 14 warps: wm in {0,1} (48 rows, 3 mma tiles), wn in {0..6} (40 cols, 5 mma tiles).
__global__ __launch_bounds__(448) void scores_tf32(
    const float* __restrict__ q, const float* __restrict__ k,
    float* __restrict__ att5)
{
    __shared__ unsigned q_s[64][104];  // [t][vq pad 96->104] conflict-free
    __shared__ unsigned k_s[68][56];   // [t (+4 halo)][vk pad 56]
    int tid = threadIdx.x;
    int lane = tid & 31;
    int w = tid >> 5;                  // 0..13
    int wm = w & 1, wn = w >> 1;       // wn 0..6
    int lr = lane >> 2, lc = lane & 3;
    int ns = blockIdx.x;
    int n = ns >> 2, s = ns & 3;
    int c0 = blockIdx.y * 4;

    float acc[3][5][4];
#pragma unroll
    for (int mt = 0; mt < 3; mt++)
#pragma unroll
        for (int nt = 0; nt < 5; nt++)
#pragma unroll
            for (int e = 0; e < 4; e++) acc[mt][nt][e] = 0.f;

#pragma unroll 1
    for (int cc = 0; cc < 4; cc++) {
        int sc = s * CC + c0 + cc;
        const float* qrow = q + (long)(n * SS * CC + sc) * COLS_Q;
        const float* krow = k + (long)(n * SS * CC + sc) * COLS_K;
#pragma unroll 1
        for (int tch = 0; tch < 4; tch++) {
            int t0 = tch * 64;
            for (int idx = tid; idx < 64 * 104; idx += 448) {
                int r = idx / 104, c = idx % 104;
                int t = t0 + r;
                float v = (t < TQ && c < VQ) ? qrow[t * VQ + c] : 0.f;
                q_s[r][c] = f2tf32(v);
            }
            for (int idx = tid; idx < 68 * 56; idx += 448) {
                int r = idx / 56, c = idx % 56;
                int t = t0 + r;
                float v = (t < TT && c < VK) ? krow[t * VK + c] : 0.f;
                k_s[r][c] = f2tf32(v);
            }
            __syncthreads();
#pragma unroll
            for (int kk = 0; kk < 64; kk += 8) {
                unsigned a[3][4];
#pragma unroll
                for (int mt = 0; mt < 3; mt++) {
                    int m0 = wm * 48 + mt * 16;
                    a[mt][0] = q_s[kk + lc][m0 + lr];
                    a[mt][1] = q_s[kk + lc][m0 + 8 + lr];
                    a[mt][2] = q_s[kk + 4 + lc][m0 + lr];
                    a[mt][3] = q_s[kk + 4 + lc][m0 + 8 + lr];
                }
                unsigned b[5][2];
#pragma unroll
                for (int nt = 0; nt < 5; nt++) {
                    int nn = wn * 40 + nt * 8;   // logical col tile (8-aligned, within one lag)
                    int l = nn / 56;
                    int vkb = nn % 56;
                    b[nt][0] = k_s[kk + lc + l][vkb + lr];
                    b[nt][1] = k_s[kk + 4 + lc + l][vkb + lr];
                }
#pragma unroll
                for (int mt = 0; mt < 3; mt++)
#pragma unroll
                    for (int nt = 0; nt < 5; nt++)
                        mma_tf32(acc[mt][nt][0], acc[mt][nt][1], acc[mt][nt][2], acc[mt][nt][3],
                                 a[mt][0], a[mt][1], a[mt][2], a[mt][3],
                                 b[nt][0], b[nt][1]);
            }
            __syncthreads();
        }
    }
    // scatter with atomics (16 c-chunk blocks contribute per element)
#pragma unroll
    for (int mt = 0; mt < 3; mt++) {
        int vq = wm * 48 + mt * 16 + lr;
#pragma unroll
        for (int nt = 0; nt < 5; nt++) {
            int nn = wn * 40 + nt * 8 + lc * 2;
            int l = nn / 56;
            int vk = nn % 56;
            long base = (((long)(l * NB + n) * SS + s) * VQ);
            if (vq < VQ) {
                if (vk < VK)     atomicAdd(&att5[(base + vq) * VK + vk], acc[mt][nt][0]);
                if (vk + 1 < VK) atomicAdd(&att5[(base + vq) * VK + vk + 1], acc[mt][nt][1]);
            }
            if (vq + 8 < VQ) {
                if (vk < VK)     atomicAdd(&att5[(base + vq + 8) * VK + vk], acc[mt][nt][2]);
                if (vk + 1 < VK) atomicAdd(&att5[(base + vq + 8) * VK + vk + 1], acc[mt][nt][3]);
            }
        }
    }
}

// ---------------- (max+mean)/2 over lags, /scale, softmax over vk ----------------
__global__ void softmax_kernel(const float* __restrict__ att5, float* __restrict__ att)
{
    int r = blockIdx.x;               // 2880 rows
    int tid = threadIdx.x;            // 64
    __shared__ float red[64];
    const float halfInv = 0.5f / sqrtf((float)(CC * TQ));
    float p = -1e30f;
    if (tid < VK) {
        float mx = -1e30f, sm = 0.f;
#pragma unroll
        for (int l = 0; l < NLAG; l++) {
            float v = att5[((long)l * (NB * SS * VQ) + r) * VK + tid];
            mx = fmaxf(mx, v);
            sm += v;
        }
        p = (mx + sm * 0.2f) * halfInv;
    }
    red[tid] = p;
    __syncthreads();
    for (int o = 32; o > 0; o >>= 1) {
        if (tid < o) red[tid] = fmaxf(red[tid], red[tid + o]);
        __syncthreads();
    }
    float m = red[0];
    __syncthreads();
    float e = (tid < VK) ? expf(p - m) : 0.f;
    red[tid] = e;
    __syncthreads();
    for (int o = 32; o > 0; o >>= 1) {
        if (tid < o) red[tid] += red[tid + o];
        __syncthreads();
    }
    if (tid < VK) att[(long)r * VK + tid] = e / red[0];
}

// ---------------- y[n,s,c,t,vq] = sum_vk att[n,s,vq,vk] * v[n,c,t,vk] (scalar, proven) ----------------
__global__ __launch_bounds__(256) void ygemm_kernel(
    const float* __restrict__ att, const float* __restrict__ v,
    float* __restrict__ y)
{
    __shared__ float att_s[96][51];
    __shared__ float v_s[64][51];
    int tid = threadIdx.x;
    int tx = tid & 15, ty = tid >> 4;
    int ns = blockIdx.y;
    int n = ns >> 2;
    int ct0 = blockIdx.x * 64;

    for (int idx = tid; idx < 96 * 51; idx += 256)
        (&att_s[0][0])[idx] = 0.f;
    __syncthreads();
    for (int idx = tid; idx < VQ * VK; idx += 256) {
        int vq = idx / VK, vk = idx % VK;
        att_s[vq][vk] = att[((long)ns * VQ + vq) * VK + vk];
    }
    const float* vb = v + (long)n * CC * COLS_K + (long)ct0 * VK;
    for (int idx = tid; idx < 64 * VK; idx += 256)
        v_s[idx / VK][idx % VK] = vb[idx];
    __syncthreads();

    float acc[4][6];
#pragma unroll
    for (int i = 0; i < 4; i++)
#pragma unroll
        for (int j = 0; j < 6; j++) acc[i][j] = 0.f;

#pragma unroll 5
    for (int vk = 0; vk < VK; vk++) {
        float a[4], b[6];
#pragma unroll
        for (int i = 0; i < 4; i++) a[i] = v_s[ty * 4 + i][vk];
#pragma unroll
        for (int j = 0; j < 6; j++) b[j] = att_s[tx * 6 + j][vk];
#pragma unroll
        for (int i = 0; i < 4; i++)
#pragma unroll
            for (int j = 0; j < 6; j++) acc[i][j] += a[i] * b[j];
    }
    long ybase = (long)ns * (CC * TT * VQ);
#pragma unroll
    for (int i = 0; i < 4; i++) {
        long ct = ct0 + ty * 4 + i;
#pragma unroll
        for (int j = 0; j < 6; j++) {
            int vq = tx * 6 + j;
            if (vq < VQ) y[ybase + ct * VQ + vq] = acc[i][j];
        }
    }
}

// ---------------- per-channel BN stats (training mode, biased var) ----------------
__global__ void stats_kernel(const float* __restrict__ o1, const float* __restrict__ d,
                             float* __restrict__ stats)
{
    int co = blockIdx.x;
    int which = blockIdx.y;
    const float* src = which ? d : o1;
    int tid = threadIdx.x;            // 256
    float sum = 0.f, sq = 0.f;
    for (int idx = tid; idx < NB * (COLS_T / 4); idx += 256) {
        int n = idx / (COLS_T / 4), c4 = idx % (COLS_T / 4);
        float4 x = *reinterpret_cast<const float4*>(
            &src[((long)n * CC + co) * COLS_T + c4 * 4]);
        sum += x.x + x.y + x.z + x.w;
        sq += x.x * x.x + x.y * x.y + x.z * x.z + x.w * x.w;
    }
    __shared__ float s1[256], s2[256];
    s1[tid] = sum; s2[tid] = sq;
    __syncthreads();
    for (int o = 128; o > 0; o >>= 1) {
        if (tid < o) { s1[tid] += s1[tid + o]; s2[tid] += s2[tid + o]; }
        __syncthreads();
    }
    if (tid == 0) {
        float M = (float)(NB * COLS_T);
        float mean = s1[0] / M;
        float var = s2[0] / M - mean * mean;
        stats[(which * CC + co) * 2 + 0] = mean;
        stats[(which * CC + co) * 2 + 1] = rsqrtf(var + BN_EPS);
    }
}

// ---------------- BN both paths + add + leaky relu (vectorized) ----------------
__global__ void final_kernel(const float* __restrict__ o1, const float* __restrict__ d,
                             const float* __restrict__ stats,
                             const float* __restrict__ gout, const float* __restrict__ bout,
                             const float* __restrict__ gdown, const float* __restrict__ bdown,
                             float* __restrict__ out)
{
    long i4 = (long)blockIdx.x * blockDim.x + threadIdx.x;
    long total4 = (long)NB * CC * COLS_T / 4;
    if (i4 >= total4) return;
    long idx = i4 * 4;
    int co = (int)((idx / COLS_T) % CC);
    float mo = stats[co * 2 + 0], iso = stats[co * 2 + 1];
    float md = stats[(CC + co) * 2 + 0], isd = stats[(CC + co) * 2 + 1];
    float so = iso * gout[co], sd = isd * gdown[co];
    float bo = bout[co] - mo * so, bd = bdown[co] - md * sd;
    float4 a = *reinterpret_cast<const float4*>(&o1[idx]);
    float4 b = *reinterpret_cast<const float4*>(&d[idx]);
    float4 r;
    float v;
    v = a.x * so + bo + b.x * sd + bd; r.x = v > 0.f ? v : 0.1f * v;
    v = a.y * so + bo + b.y * sd + bd; r.y = v > 0.f ? v : 0.1f * v;
    v = a.z * so + bo + b.z * sd + bd; r.z = v > 0.f ? v : 0.1f * v;
    v = a.w * so + bo + b.w * sd + bd; r.w = v > 0.f ? v : 0.1f * v;
    *reinterpret_cast<float4*>(&out[idx]) = r;
}

// ---------------- launch ----------------
extern "C" void kernel_launch(void* const* d_in, const int* in_sizes, int n_in,
                              void* d_out, int out_size)
{
    const float* x_q   = (const float*)d_in[0];
    const float* x_k   = (const float*)d_in[1];
    const float* x_v   = (const float*)d_in[2];
    const float* Wq    = (const float*)d_in[3];
    const float* bq    = (const float*)d_in[4];
    const float* Wk    = (const float*)d_in[5];
    const float* bk    = (const float*)d_in[6];
    const float* Wv    = (const float*)d_in[7];
    const float* bv    = (const float*)d_in[8];
    const float* Wout  = (const float*)d_in[9];
    const float* bout  = (const float*)d_in[10];
    const float* g_out = (const float*)d_in[11];
    const float* b_out = (const float*)d_in[12];
    const float* Wdown = (const float*)d_in[13];
    const float* bdown = (const float*)d_in[14];
    const float* g_dn  = (const float*)d_in[15];
    const float* b_dn  = (const float*)d_in[16];

    float *q, *k, *v, *y, *o1, *db, *att5, *att, *stats;
    cudaGetSymbolAddress((void**)&q,     g_q);
    cudaGetSymbolAddress((void**)&k,     g_k);
    cudaGetSymbolAddress((void**)&v,     g_v);
    cudaGetSymbolAddress((void**)&y,     g_y);
    cudaGetSymbolAddress((void**)&o1,    g_o1);
    cudaGetSymbolAddress((void**)&db,    g_d);
    cudaGetSymbolAddress((void**)&att5,  g_att5);
    cudaGetSymbolAddress((void**)&att,   g_att);
    cudaGetSymbolAddress((void**)&stats, g_stats);

    int natt5 = NLAG * NB * SS * VQ * VK;
    zero_kernel<<<(natt5 + 255) / 256, 256>>>(att5, natt5);

    // projections (tf32 mma)
    gemm_tf32<<<dim3((COLS_Q + 127) / 128, (SS * CC) / 64, NB), 128>>>(
        Wq, bq, x_q, q, CC, COLS_Q, COLS_T, (long)CC * COLS_T, (long)SS * CC * COLS_Q);
    gemm_tf32<<<dim3(COLS_K / 128, (SS * CC) / 64, NB), 128>>>(
        Wk, bk, x_k, k, CC, COLS_K, COLS_K, (long)CC * COLS_K, (long)SS * CC * COLS_K);
    gemm_tf32<<<dim3(COLS_K / 128, 1, NB), 128>>>(
        Wv, bv, x_v, v, CC, COLS_K, COLS_K, (long)CC * COLS_K, (long)CC * COLS_K);

    // multi-lag scores (tf32 mma) + softmax
    scores_tf32<<<dim3(NB * SS, 16), 448>>>(q, k, att5);
    softmax_kernel<<<NB * SS * VQ, 64>>>(att5, att);

    // y = att @ v
    ygemm_kernel<<<dim3((CC * TT) / 64, NB * SS), 256>>>(att, v, y);

    // output / downsample projections (tf32 mma)
    gemm_tf32<<<dim3(COLS_T / 128, 1, NB), 128>>>(
        Wout, bout, y, o1, SS * CC, COLS_T, COLS_T, (long)SS * CC * COLS_T, (long)CC * COLS_T);
    gemm_tf32<<<dim3(COLS_T / 128, 1, NB), 128>>>(
        Wdown, bdown, x_q, db, CC, COLS_T, COLS_T, (long)CC * COLS_T, (long)CC * COLS_T);

    // BN stats + fused epilogue
    stats_kernel<<<dim3(CC, 2), 256>>>(o1, db, stats);
    long total4 = (long)NB * CC * COLS_T / 4;
    final_kernel<<<(unsigned)((total4 + 255) / 256), 256>>>(
        o1, db, stats, g_out, b_out, g_dn, b_dn, (float*)d_out);
}

// round 9
// speedup vs baseline: 3.5152x; 1.9843x over previous
#include <cuda_runtime.h>

#define NB 8
#define CC 64
#define TT 256
#define VQ 90
#define VK 50
#define SS 4
#define LAG 4
#define NLAG (LAG + 1)
#define TQ (TT - LAG)                 // 252
#define COLS_Q (TQ * VQ)              // 22680
#define COLS_T (TT * VQ)              // 23040
#define COLS_K (TT * VK)              // 12800
#define BN_EPS 1e-5f

// ---------------- tf32 mma helpers ----------------
__device__ __forceinline__ unsigned f2tf32(float x) {
    unsigned r;
    asm("cvt.rna.tf32.f32 %0, %1;" : "=r"(r) : "f"(x));
    return r;
}
__device__ __forceinline__ void mma_tf32(
    float& c0, float& c1, float& c2, float& c3,
    unsigned a0, unsigned a1, unsigned a2, unsigned a3,
    unsigned b0, unsigned b1)
{
    asm("mma.sync.aligned.m16n8k8.row.col.f32.tf32.tf32.f32 "
        "{%0,%1,%2,%3},{%4,%5,%6,%7},{%8,%9},{%0,%1,%2,%3};"
        : "+f"(c0), "+f"(c1), "+f"(c2), "+f"(c3)
        : "r"(a0), "r"(a1), "r"(a2), "r"(a3), "r"(b0), "r"(b1));
}

// ---------------- scratch (static device memory; no allocations) ----------------
__device__ float g_q   [NB * SS * CC * COLS_Q];
__device__ float g_k   [NB * SS * CC * COLS_K];
__device__ float g_v   [NB * CC * COLS_K];
__device__ float g_y   [NB * SS * CC * COLS_T];
__device__ float g_o1  [NB * CC * COLS_T];
__device__ float g_d   [NB * CC * COLS_T];
__device__ float g_att5[NLAG * NB * SS * VQ * VK];
__device__ float g_att [NB * SS * VQ * VK];
__device__ float g_stats[2 * CC * 2];

// ---------------- zero kernel ----------------
__global__ void zero_kernel(float* p, int n) {
    int i = blockIdx.x * blockDim.x + threadIdx.x;
    if (i < n) p[i] = 0.f;
}

// ---------------- conv1x1 GEMM via tf32 mma: O[n][r][col] = sum_k W[r][k] X[n][k][col] + b[r] ----------------
// Block tile: 64 rows x 256 cols, K-chunk 32. 8 warps (2 M x 4 N), warp tile 32x64.
__global__ __launch_bounds__(256) void gemm_tf32(
    const float* __restrict__ W, const float* __restrict__ bias,
    const float* __restrict__ X, float* __restrict__ O,
    int K, int cols, int rsB, long bsB, long bsC)
{
    __shared__ unsigned Ws[64][36];   // [m][k], stride 36 -> conflict-free frags
    __shared__ unsigned Xs[32][264];  // [k][n], stride 264 -> conflict-free frags
    int tid = threadIdx.x;
    int lane = tid & 31;
    int w = tid >> 5;
    int wm = w & 1, wn = w >> 1;      // wn 0..3
    int lr = lane >> 2, lc = lane & 3;
    int n = blockIdx.z;
    int row0 = blockIdx.y * 64;
    int col0 = blockIdx.x * 256;
    const float* Xn = X + (long)n * bsB;

    float acc[2][8][4];
#pragma unroll
    for (int mt = 0; mt < 2; mt++)
#pragma unroll
        for (int nt = 0; nt < 8; nt++)
#pragma unroll
            for (int e = 0; e < 4; e++) acc[mt][nt][e] = 0.f;

    for (int kc = 0; kc < K; kc += 32) {
        // Ws[m][k] <- W[(row0+m)*K + kc+k] : 64x32 = 512 float4
#pragma unroll
        for (int it = 0; it < 2; it++) {
            int idx = tid + it * 256;
            int r = idx >> 3, q4 = idx & 7;
            float4 wv = *reinterpret_cast<const float4*>(&W[(long)(row0 + r) * K + kc + q4 * 4]);
            Ws[r][q4 * 4 + 0] = f2tf32(wv.x);
            Ws[r][q4 * 4 + 1] = f2tf32(wv.y);
            Ws[r][q4 * 4 + 2] = f2tf32(wv.z);
            Ws[r][q4 * 4 + 3] = f2tf32(wv.w);
        }
        // Xs[k][c] <- X[(kc+k)*rsB + col0+c] : 32x256 = 2048 float4
#pragma unroll
        for (int it = 0; it < 8; it++) {
            int idx = tid + it * 256;
            int kk = idx >> 6, c4 = idx & 63;
            int col = col0 + c4 * 4;
            float4 xv = make_float4(0.f, 0.f, 0.f, 0.f);
            if (col < cols)
                xv = *reinterpret_cast<const float4*>(&Xn[(long)(kc + kk) * rsB + col]);
            Xs[kk][c4 * 4 + 0] = f2tf32(xv.x);
            Xs[kk][c4 * 4 + 1] = f2tf32(xv.y);
            Xs[kk][c4 * 4 + 2] = f2tf32(xv.z);
            Xs[kk][c4 * 4 + 3] = f2tf32(xv.w);
        }
        __syncthreads();
#pragma unroll
        for (int kk = 0; kk < 32; kk += 8) {
            unsigned a[2][4];
#pragma unroll
            for (int mt = 0; mt < 2; mt++) {
                int m0 = wm * 32 + mt * 16;
                a[mt][0] = Ws[m0 + lr][kk + lc];
                a[mt][1] = Ws[m0 + 8 + lr][kk + lc];
                a[mt][2] = Ws[m0 + lr][kk + 4 + lc];
                a[mt][3] = Ws[m0 + 8 + lr][kk + 4 + lc];
            }
            unsigned b[8][2];
#pragma unroll
            for (int nt = 0; nt < 8; nt++) {
                int n0 = wn * 64 + nt * 8;
                b[nt][0] = Xs[kk + lc][n0 + lr];
                b[nt][1] = Xs[kk + 4 + lc][n0 + lr];
            }
#pragma unroll
            for (int mt = 0; mt < 2; mt++)
#pragma unroll
                for (int nt = 0; nt < 8; nt++)
                    mma_tf32(acc[mt][nt][0], acc[mt][nt][1], acc[mt][nt][2], acc[mt][nt][3],
                             a[mt][0], a[mt][1], a[mt][2], a[mt][3],
                             b[nt][0], b[nt][1]);
        }
        __syncthreads();
    }
    // epilogue
#pragma unroll
    for (int mt = 0; mt < 2; mt++) {
        int r0 = row0 + wm * 32 + mt * 16 + lr;
        float bv0 = bias[r0], bv8 = bias[r0 + 8];
        float* orow0 = O + (long)n * bsC + (long)r0 * cols;
        float* orow8 = orow0 + (long)8 * cols;
#pragma unroll
        for (int nt = 0; nt < 8; nt++) {
            int col = col0 + wn * 64 + nt * 8 + lc * 2;
            if (col < cols) {
                *reinterpret_cast<float2*>(&orow0[col]) =
                    make_float2(acc[mt][nt][0] + bv0, acc[mt][nt][1] + bv0);
                *reinterpret_cast<float2*>(&orow8[col]) =
                    make_float2(acc[mt][nt][2] + bv8, acc[mt][nt][3] + bv8);
            }
        }
    }
}

// ---------------- 5-lag attention scores via tf32 mma, software-pipelined ----------------
// For block (ns, c-chunk of 4): C[vq, (l,vk)] += sum_{c,t} q[c,t,vq] * k[c,t+l,vk]
// 16 chunks = 4 channels x 4 t-chunks of 64. Register prefetch overlaps gmem with mma.
#define SC_NQ 13                     // ceil(64*90 / 448)
#define SC_NK 8                      // ceil(68*50 / 448)
__global__ __launch_bounds__(448) void scores_tf32(
    const float* __restrict__ q, const float* __restrict__ k,
    float* __restrict__ att5)
{
    __shared__ unsigned q_s[64][104];  // [t][vq pad 90->104]
    __shared__ unsigned k_s[68][56];   // [t (+4 halo)][vk pad 50->56]
    int tid = threadIdx.x;
    int lane = tid & 31;
    int w = tid >> 5;                  // 0..13
    int wm = w & 1, wn = w >> 1;       // wn 0..6
    int lr = lane >> 2, lc = lane & 3;
    int ns = blockIdx.x;
    int n = ns >> 2, s = ns & 3;
    int c0 = blockIdx.y * 4;

    const float* qbase = q + (long)(n * SS * CC + s * CC + c0) * COLS_Q;
    const float* kbase = k + (long)(n * SS * CC + s * CC + c0) * COLS_K;

    // hoisted lag decomposition per nt
    int lagv[5], vkbv[5];
#pragma unroll
    for (int nt = 0; nt < 5; nt++) {
        int nn = wn * 40 + nt * 8;
        lagv[nt] = nn / 56;
        vkbv[nt] = nn % 56 + lr;
    }

    float acc[3][5][4];
#pragma unroll
    for (int mt = 0; mt < 3; mt++)
#pragma unroll
        for (int nt = 0; nt < 5; nt++)
#pragma unroll
            for (int e = 0; e < 4; e++) acc[mt][nt][e] = 0.f;

    // zero all smem once (pads stay zero; real cols overwritten each chunk)
    for (int idx = tid; idx < 64 * 104; idx += 448) (&q_s[0][0])[idx] = 0u;
    for (int idx = tid; idx < 68 * 56; idx += 448) (&k_s[0][0])[idx] = 0u;

    float qv[SC_NQ], kv[SC_NK];
    // ---- prefetch chunk 0 ----
    {
        const float* qr = qbase;     // cc=0, t0=0
        const float* kr = kbase;
#pragma unroll
        for (int i = 0; i < SC_NQ; i++) {
            int idx = tid + i * 448;
            qv[i] = (idx < 64 * VQ) ? qr[idx] : 0.f;
        }
#pragma unroll
        for (int i = 0; i < SC_NK; i++) {
            int idx = tid + i * 448;
            kv[i] = (idx < 68 * VK) ? kr[idx] : 0.f;
        }
    }
    __syncthreads();                 // zero-fill visible
    // store chunk 0
#pragma unroll
    for (int i = 0; i < SC_NQ; i++) {
        int idx = tid + i * 448;
        if (idx < 64 * VQ) { int r = idx / VQ, c = idx - r * VQ; q_s[r][c] = f2tf32(qv[i]); }
    }
#pragma unroll
    for (int i = 0; i < SC_NK; i++) {
        int idx = tid + i * 448;
        if (idx < 68 * VK) { int r = idx / VK, c = idx - r * VK; k_s[r][c] = f2tf32(kv[i]); }
    }

#pragma unroll 1
    for (int chunk = 0; chunk < 16; chunk++) {
        __syncthreads();             // current chunk smem ready
        // prefetch next chunk into regs (overlaps with mma below)
        int nxt = chunk + 1;
        if (nxt < 16) {
            int cc = nxt >> 2, tch = nxt & 3;
            int t0 = tch * 64;
            const float* qr = qbase + (long)cc * COLS_Q + (long)t0 * VQ;
            int qlim = (TQ - t0) * VQ; if (qlim > 64 * VQ) qlim = 64 * VQ;
            const float* kr = kbase + (long)cc * COLS_K + (long)t0 * VK;
            int klim = (TT - t0) * VK; if (klim > 68 * VK) klim = 68 * VK;
#pragma unroll
            for (int i = 0; i < SC_NQ; i++) {
                int idx = tid + i * 448;
                qv[i] = (idx < qlim) ? qr[idx] : 0.f;
            }
#pragma unroll
            for (int i = 0; i < SC_NK; i++) {
                int idx = tid + i * 448;
                kv[i] = (idx < klim) ? kr[idx] : 0.f;
            }
        }
        // compute on current chunk
#pragma unroll
        for (int kk = 0; kk < 64; kk += 8) {
            unsigned a[3][4];
#pragma unroll
            for (int mt = 0; mt < 3; mt++) {
                int m0 = wm * 48 + mt * 16;
                a[mt][0] = q_s[kk + lc][m0 + lr];
                a[mt][1] = q_s[kk + lc][m0 + 8 + lr];
                a[mt][2] = q_s[kk + 4 + lc][m0 + lr];
                a[mt][3] = q_s[kk + 4 + lc][m0 + 8 + lr];
            }
            unsigned b[5][2];
#pragma unroll
            for (int nt = 0; nt < 5; nt++) {
                b[nt][0] = k_s[kk + lc + lagv[nt]][vkbv[nt]];
                b[nt][1] = k_s[kk + 4 + lc + lagv[nt]][vkbv[nt]];
            }
#pragma unroll
            for (int mt = 0; mt < 3; mt++)
#pragma unroll
                for (int nt = 0; nt < 5; nt++)
                    mma_tf32(acc[mt][nt][0], acc[mt][nt][1], acc[mt][nt][2], acc[mt][nt][3],
                             a[mt][0], a[mt][1], a[mt][2], a[mt][3],
                             b[nt][0], b[nt][1]);
        }
        __syncthreads();             // all reads done
        if (nxt < 16) {
            // store next chunk regs -> smem
#pragma unroll
            for (int i = 0; i < SC_NQ; i++) {
                int idx = tid + i * 448;
                if (idx < 64 * VQ) { int r = idx / VQ, c = idx - r * VQ; q_s[r][c] = f2tf32(qv[i]); }
            }
#pragma unroll
            for (int i = 0; i < SC_NK; i++) {
                int idx = tid + i * 448;
                if (idx < 68 * VK) { int r = idx / VK, c = idx - r * VK; k_s[r][c] = f2tf32(kv[i]); }
            }
        }
    }

    // scatter with atomics (16 c-chunk blocks contribute per element)
#pragma unroll
    for (int mt = 0; mt < 3; mt++) {
        int vq = wm * 48 + mt * 16 + lr;
#pragma unroll
        for (int nt = 0; nt < 5; nt++) {
            int nn = wn * 40 + nt * 8 + lc * 2;
            int l = nn / 56;
            int vk = nn % 56;
            long base = (((long)(l * NB + n) * SS + s) * VQ);
            if (vq < VQ) {
                if (vk < VK)     atomicAdd(&att5[(base + vq) * VK + vk], acc[mt][nt][0]);
                if (vk + 1 < VK) atomicAdd(&att5[(base + vq) * VK + vk + 1], acc[mt][nt][1]);
            }
            if (vq + 8 < VQ) {
                if (vk < VK)     atomicAdd(&att5[(base + vq + 8) * VK + vk], acc[mt][nt][2]);
                if (vk + 1 < VK) atomicAdd(&att5[(base + vq + 8) * VK + vk + 1], acc[mt][nt][3]);
            }
        }
    }
}

// ---------------- (max+mean)/2 over lags, /scale, softmax over vk ----------------
__global__ void softmax_kernel(const float* __restrict__ att5, float* __restrict__ att)
{
    int r = blockIdx.x;               // 2880 rows
    int tid = threadIdx.x;            // 64
    __shared__ float red[64];
    const float halfInv = 0.5f / sqrtf((float)(CC * TQ));
    float p = -1e30f;
    if (tid < VK) {
        float mx = -1e30f, sm = 0.f;
#pragma unroll
        for (int l = 0; l < NLAG; l++) {
            float v = att5[((long)l * (NB * SS * VQ) + r) * VK + tid];
            mx = fmaxf(mx, v);
            sm += v;
        }
        p = (mx + sm * 0.2f) * halfInv;
    }
    red[tid] = p;
    __syncthreads();
    for (int o = 32; o > 0; o >>= 1) {
        if (tid < o) red[tid] = fmaxf(red[tid], red[tid + o]);
        __syncthreads();
    }
    float m = red[0];
    __syncthreads();
    float e = (tid < VK) ? expf(p - m) : 0.f;
    red[tid] = e;
    __syncthreads();
    for (int o = 32; o > 0; o >>= 1) {
        if (tid < o) red[tid] += red[tid + o];
        __syncthreads();
    }
    if (tid < VK) att[(long)r * VK + tid] = e / red[0];
}

// ---------------- y[ns][ct][vq] = sum_vk v[n][ct][vk] * att[ns][vq][vk] via tf32 mma ----------------
// Block: 64 ct-rows x 96 vq-cols, K=56 (vk padded). 8 warps (2 M x 4 N), warp 32x24.
__global__ __launch_bounds__(256) void ygemm_tf32(
    const float* __restrict__ att, const float* __restrict__ v,
    float* __restrict__ y)
{
    __shared__ unsigned vt_s[64][60];   // [ct][vk pad 50->56, stride 60 conflict-free]
    __shared__ unsigned at_s[56][104];  // [vk][vq pad 90->96, stride 104]
    int tid = threadIdx.x;
    int lane = tid & 31;
    int w = tid >> 5;
    int wm = w & 1, wn = w >> 1;        // wn 0..3
    int lr = lane >> 2, lc = lane & 3;
    int ns = blockIdx.y;
    int n = ns >> 2;
    int ct0 = blockIdx.x * 64;

    for (int idx = tid; idx < 64 * 60; idx += 256) (&vt_s[0][0])[idx] = 0u;
    for (int idx = tid; idx < 56 * 104; idx += 256) (&at_s[0][0])[idx] = 0u;
    __syncthreads();
    const float* ab = att + (long)ns * (VQ * VK);
    for (int idx = tid; idx < VQ * VK; idx += 256) {
        int vq = idx / VK, vk = idx - vq * VK;
        at_s[vk][vq] = f2tf32(ab[idx]);
    }
    const float* vb = v + (long)n * CC * COLS_K + (long)ct0 * VK;
    for (int idx = tid; idx < 64 * VK; idx += 256) {
        int r = idx / VK, c = idx - r * VK;
        vt_s[r][c] = f2tf32(vb[idx]);
    }
    __syncthreads();

    float acc[2][3][4];
#pragma unroll
    for (int mt = 0; mt < 2; mt++)
#pragma unroll
        for (int nt = 0; nt < 3; nt++)
#pragma unroll
            for (int e = 0; e < 4; e++) acc[mt][nt][e] = 0.f;

#pragma unroll
    for (int kk = 0; kk < 56; kk += 8) {
        unsigned a[2][4];
#pragma unroll
        for (int mt = 0; mt < 2; mt++) {
            int m0 = wm * 32 + mt * 16;
            a[mt][0] = vt_s[m0 + lr][kk + lc];
            a[mt][1] = vt_s[m0 + 8 + lr][kk + lc];
            a[mt][2] = vt_s[m0 + lr][kk + 4 + lc];
            a[mt][3] = vt_s[m0 + 8 + lr][kk + 4 + lc];
        }
        unsigned b[3][2];
#pragma unroll
        for (int nt = 0; nt < 3; nt++) {
            int n0 = wn * 24 + nt * 8;
            b[nt][0] = at_s[kk + lc][n0 + lr];
            b[nt][1] = at_s[kk + 4 + lc][n0 + lr];
        }
#pragma unroll
        for (int mt = 0; mt < 2; mt++)
#pragma unroll
            for (int nt = 0; nt < 3; nt++)
                mma_tf32(acc[mt][nt][0], acc[mt][nt][1], acc[mt][nt][2], acc[mt][nt][3],
                         a[mt][0], a[mt][1], a[mt][2], a[mt][3],
                         b[nt][0], b[nt][1]);
    }

    long ybase = (long)ns * ((long)CC * TT * VQ);
#pragma unroll
    for (int mt = 0; mt < 2; mt++) {
        long row = ct0 + wm * 32 + mt * 16 + lr;
#pragma unroll
        for (int nt = 0; nt < 3; nt++) {
            int col = wn * 24 + nt * 8 + lc * 2;
            if (col < VQ) {
                *reinterpret_cast<float2*>(&y[ybase + row * VQ + col]) =
                    make_float2(acc[mt][nt][0], acc[mt][nt][1]);
                *reinterpret_cast<float2*>(&y[ybase + (row + 8) * VQ + col]) =
                    make_float2(acc[mt][nt][2], acc[mt][nt][3]);
            }
        }
    }
}

// ---------------- per-channel BN stats (training mode, biased var) ----------------
__global__ void stats_kernel(const float* __restrict__ o1, const float* __restrict__ d,
                             float* __restrict__ stats)
{
    int co = blockIdx.x;
    int which = blockIdx.y;
    const float* src = which ? d : o1;
    int tid = threadIdx.x;            // 256
    float sum = 0.f, sq = 0.f;
    for (int idx = tid; idx < NB * (COLS_T / 4); idx += 256) {
        int n = idx / (COLS_T / 4), c4 = idx % (COLS_T / 4);
        float4 x = *reinterpret_cast<const float4*>(
            &src[((long)n * CC + co) * COLS_T + c4 * 4]);
        sum += x.x + x.y + x.z + x.w;
        sq += x.x * x.x + x.y * x.y + x.z * x.z + x.w * x.w;
    }
    __shared__ float s1[256], s2[256];
    s1[tid] = sum; s2[tid] = sq;
    __syncthreads();
    for (int o = 128; o > 0; o >>= 1) {
        if (tid < o) { s1[tid] += s1[tid + o]; s2[tid] += s2[tid + o]; }
        __syncthreads();
    }
    if (tid == 0) {
        float M = (float)(NB * COLS_T);
        float mean = s1[0] / M;
        float var = s2[0] / M - mean * mean;
        stats[(which * CC + co) * 2 + 0] = mean;
        stats[(which * CC + co) * 2 + 1] = rsqrtf(var + BN_EPS);
    }
}

// ---------------- BN both paths + add + leaky relu (vectorized) ----------------
__global__ void final_kernel(const float* __restrict__ o1, const float* __restrict__ d,
                             const float* __restrict__ stats,
                             const float* __restrict__ gout, const float* __restrict__ bout,
                             const float* __restrict__ gdown, const float* __restrict__ bdown,
                             float* __restrict__ out)
{
    long i4 = (long)blockIdx.x * blockDim.x + threadIdx.x;
    long total4 = (long)NB * CC * COLS_T / 4;
    if (i4 >= total4) return;
    long idx = i4 * 4;
    int co = (int)((idx / COLS_T) % CC);
    float mo = stats[co * 2 + 0], iso = stats[co * 2 + 1];
    float md = stats[(CC + co) * 2 + 0], isd = stats[(CC + co) * 2 + 1];
    float so = iso * gout[co], sd = isd * gdown[co];
    float bo = bout[co] - mo * so, bd = bdown[co] - md * sd;
    float4 a = *reinterpret_cast<const float4*>(&o1[idx]);
    float4 b = *reinterpret_cast<const float4*>(&d[idx]);
    float4 r;
    float v;
    v = a.x * so + bo + b.x * sd + bd; r.x = v > 0.f ? v : 0.1f * v;
    v = a.y * so + bo + b.y * sd + bd; r.y = v > 0.f ? v : 0.1f * v;
    v = a.z * so + bo + b.z * sd + bd; r.z = v > 0.f ? v : 0.1f * v;
    v = a.w * so + bo + b.w * sd + bd; r.w = v > 0.f ? v : 0.1f * v;
    *reinterpret_cast<float4*>(&out[idx]) = r;
}

// ---------------- launch ----------------
extern "C" void kernel_launch(void* const* d_in, const int* in_sizes, int n_in,
                              void* d_out, int out_size)
{
    const float* x_q   = (const float*)d_in[0];
    const float* x_k   = (const float*)d_in[1];
    const float* x_v   = (const float*)d_in[2];
    const float* Wq    = (const float*)d_in[3];
    const float* bq    = (const float*)d_in[4];
    const float* Wk    = (const float*)d_in[5];
    const float* bk    = (const float*)d_in[6];
    const float* Wv    = (const float*)d_in[7];
    const float* bv    = (const float*)d_in[8];
    const float* Wout  = (const float*)d_in[9];
    const float* bout  = (const float*)d_in[10];
    const float* g_out = (const float*)d_in[11];
    const float* b_out = (const float*)d_in[12];
    const float* Wdown = (const float*)d_in[13];
    const float* bdown = (const float*)d_in[14];
    const float* g_dn  = (const float*)d_in[15];
    const float* b_dn  = (const float*)d_in[16];

    float *q, *k, *v, *y, *o1, *db, *att5, *att, *stats;
    cudaGetSymbolAddress((void**)&q,     g_q);
    cudaGetSymbolAddress((void**)&k,     g_k);
    cudaGetSymbolAddress((void**)&v,     g_v);
    cudaGetSymbolAddress((void**)&y,     g_y);
    cudaGetSymbolAddress((void**)&o1,    g_o1);
    cudaGetSymbolAddress((void**)&db,    g_d);
    cudaGetSymbolAddress((void**)&att5,  g_att5);
    cudaGetSymbolAddress((void**)&att,   g_att);
    cudaGetSymbolAddress((void**)&stats, g_stats);

    int natt5 = NLAG * NB * SS * VQ * VK;
    zero_kernel<<<(natt5 + 255) / 256, 256>>>(att5, natt5);

    // projections (tf32 mma)
    gemm_tf32<<<dim3((COLS_Q + 255) / 256, (SS * CC) / 64, NB), 256>>>(
        Wq, bq, x_q, q, CC, COLS_Q, COLS_T, (long)CC * COLS_T, (long)SS * CC * COLS_Q);
    gemm_tf32<<<dim3(COLS_K / 256, (SS * CC) / 64, NB), 256>>>(
        Wk, bk, x_k, k, CC, COLS_K, COLS_K, (long)CC * COLS_K, (long)SS * CC * COLS_K);
    gemm_tf32<<<dim3(COLS_K / 256, 1, NB), 256>>>(
        Wv, bv, x_v, v, CC, COLS_K, COLS_K, (long)CC * COLS_K, (long)CC * COLS_K);

    // multi-lag scores (tf32 mma, pipelined) + softmax
    scores_tf32<<<dim3(NB * SS, 16), 448>>>(q, k, att5);
    softmax_kernel<<<NB * SS * VQ, 64>>>(att5, att);

    // y = att @ v (tf32 mma)
    ygemm_tf32<<<dim3((CC * TT) / 64, NB * SS), 256>>>(att, v, y);

    // output / downsample projections (tf32 mma)
    gemm_tf32<<<dim3(COLS_T / 256, 1, NB), 256>>>(
        Wout, bout, y, o1, SS * CC, COLS_T, COLS_T, (long)SS * CC * COLS_T, (long)CC * COLS_T);
    gemm_tf32<<<dim3(COLS_T / 256, 1, NB), 256>>>(
        Wdown, bdown, x_q, db, CC, COLS_T, COLS_T, (long)CC * COLS_T, (long)CC * COLS_T);

    // BN stats + fused epilogue
    stats_kernel<<<dim3(CC, 2), 256>>>(o1, db, stats);
    long total4 = (long)NB * CC * COLS_T / 4;
    final_kernel<<<(unsigned)((total4 + 255) / 256), 256>>>(
        o1, db, stats, g_out, b_out, g_dn, b_dn, (float*)d_out);
}